// round 9
// baseline (speedup 1.0000x reference)
#include <cuda_runtime.h>
#include <cstdint>

#define DEV_INLINE __device__ __forceinline__

#if defined(__CUDA_ARCH__) && defined(__CUDA_ARCH_FEAT_SM103_ALL)
#define HAS_TCGEN05 1
#else
#define HAS_TCGEN05 0
#endif

constexpr int BATCH = 16;
constexpr int L = 2048;
constexpr int D = 1024;
constexpr int NT_STRIDE = 16;       // partial-sum slots per row
constexpr int STAGES = 3;
constexpr int STAGE_BYTES = 65536;  // 32KB A + 32KB B
constexpr int SMEM_TC = 1024 + STAGES * STAGE_BYTES;      // 197632
constexpr int SMEM_FB = (4 * 128 * 36) * 4;               // 73728

// ---- scratch (static: no cudaMalloc allowed) ----
__device__ float g_KT[(size_t)BATCH * L * D];
__device__ float g_VT[(size_t)BATCH * D * L];
__device__ float g_Qr[(size_t)BATCH * L * D];
__device__ float g_Kr[(size_t)BATCH * L * D];
__device__ float g_Wr[(size_t)D * D];
__device__ float g_P [(size_t)BATCH * L * L];               // unnormalized exp scores
__device__ float g_partial[(size_t)BATCH * L * NT_STRIDE];  // zero-init
__device__ float g_linv[(size_t)BATCH * L];

// ---------------- common helpers ----------------
DEV_INLINE uint32_t f2tf(float f) {
    uint32_t u;
    asm("cvt.rna.tf32.f32 %0, %1;" : "=r"(u) : "f"(f));
    return u;
}
DEV_INLINE float rna_tf32(float f) { return __uint_as_float(f2tf(f)); }

DEV_INLINE uint32_t smem_u32(const void* p) {
    uint32_t a;
    asm("{ .reg .u64 t; cvta.to.shared.u64 t, %1; cvt.u32.u64 %0, t; }" : "=r"(a) : "l"(p));
    return a;
}
DEV_INLINE void cp16(uint32_t s, const float* g) {
    asm volatile("cp.async.cg.shared.global [%0], [%1], 16;" :: "r"(s), "l"(g));
}
DEV_INLINE void cp16p(float* s, const float* g) {
    uint32_t sa = (uint32_t)__cvta_generic_to_shared(s);
    asm volatile("cp.async.cg.shared.global [%0], [%1], 16;" :: "r"(sa), "l"(g));
}
DEV_INLINE void cp_commit() { asm volatile("cp.async.commit_group;" ::: "memory"); }
template <int N> DEV_INLINE void cp_wait() {
    asm volatile("cp.async.wait_group %0;" :: "n"(N) : "memory");
}
DEV_INLINE uint32_t swz(uint32_t o) { return o ^ ((o >> 3) & 0x70); }

// =====================================================================
// tcgen05 cg1 path (only materialized for compute_103a)
// =====================================================================
#if HAS_TCGEN05
DEV_INLINE uint32_t elect_one() {
    uint32_t p;
    asm volatile("{ .reg .pred P; elect.sync _|P, 0xFFFFFFFF; selp.b32 %0, 1, 0, P; }" : "=r"(p));
    return p;
}
DEV_INLINE void mbar_init(uint32_t m, uint32_t cnt) {
    asm volatile("mbarrier.init.shared.b64 [%0], %1;" :: "r"(m), "r"(cnt) : "memory");
}
DEV_INLINE void mbar_wait(uint32_t m, uint32_t parity) {
    asm volatile(
        "{\n\t.reg .pred P;\n\t"
        "WL%=:\n\t"
        "mbarrier.try_wait.parity.acquire.cta.shared::cta.b64 P, [%0], %1, 0x989680;\n\t"
        "@P bra.uni WD%=;\n\t"
        "bra.uni WL%=;\n\t"
        "WD%=:\n\t}"
        :: "r"(m), "r"(parity) : "memory");
}
DEV_INLINE void tmem_alloc(uint32_t smem_dst, uint32_t ncols) {
    asm volatile("tcgen05.alloc.cta_group::1.sync.aligned.shared::cta.b32 [%0], %1;"
                 :: "r"(smem_dst), "r"(ncols) : "memory");
}
DEV_INLINE void tmem_dealloc(uint32_t tmem, uint32_t ncols) {
    asm volatile("tcgen05.dealloc.cta_group::1.sync.aligned.b32 %0, %1;" :: "r"(tmem), "r"(ncols));
}
DEV_INLINE void tmem_relinquish() {
    asm volatile("tcgen05.relinquish_alloc_permit.cta_group::1.sync.aligned;");
}
DEV_INLINE void mma_tf32_ss(uint32_t d, uint64_t a, uint64_t b, uint32_t idesc, uint32_t en) {
    asm volatile(
        "{\n\t.reg .pred p;\n\t"
        "setp.ne.u32 p, %5, 0;\n\t"
        "tcgen05.mma.cta_group::1.kind::tf32 [%0], %1, %2, %3, {%4,%4,%4,%4}, p;\n\t}"
        :: "r"(d), "l"(a), "l"(b), "r"(idesc), "r"(0u), "r"(en) : "memory");
}
DEV_INLINE void tc_commit(uint32_t mbar) {
    asm volatile("tcgen05.commit.cta_group::1.mbarrier::arrive::one.shared::cluster.b64 [%0];"
                 :: "r"(mbar) : "memory");
}
DEV_INLINE void fence_async() { asm volatile("fence.proxy.async.shared::cta;" ::: "memory"); }
DEV_INLINE void tc_fence_after() { asm volatile("tcgen05.fence::after_thread_sync;" ::: "memory"); }
DEV_INLINE void tc_wait_ld() { asm volatile("tcgen05.wait::ld.sync.aligned;" ::: "memory"); }

#define LDTM32(r, addr)                                                        \
    asm volatile("tcgen05.ld.sync.aligned.32x32b.x32.b32 "                      \
        "{%0,%1,%2,%3,%4,%5,%6,%7,%8,%9,%10,%11,%12,%13,%14,%15,"               \
        "%16,%17,%18,%19,%20,%21,%22,%23,%24,%25,%26,%27,%28,%29,%30,%31}, [%32];" \
        : "=r"((r)[0]), "=r"((r)[1]), "=r"((r)[2]), "=r"((r)[3]),               \
          "=r"((r)[4]), "=r"((r)[5]), "=r"((r)[6]), "=r"((r)[7]),               \
          "=r"((r)[8]), "=r"((r)[9]), "=r"((r)[10]), "=r"((r)[11]),             \
          "=r"((r)[12]), "=r"((r)[13]), "=r"((r)[14]), "=r"((r)[15]),           \
          "=r"((r)[16]), "=r"((r)[17]), "=r"((r)[18]), "=r"((r)[19]),           \
          "=r"((r)[20]), "=r"((r)[21]), "=r"((r)[22]), "=r"((r)[23]),           \
          "=r"((r)[24]), "=r"((r)[25]), "=r"((r)[26]), "=r"((r)[27]),           \
          "=r"((r)[28]), "=r"((r)[29]), "=r"((r)[30]), "=r"((r)[31])            \
        : "r"(addr))

constexpr uint64_t DESC_BASE_SW128 =
    (2ULL << 61) | (1ULL << 46) | (64ULL << 32) | (1ULL << 16);
// idesc kind::tf32: dtype=F32(1)<<4, atype=TF32(2)<<7, btype=TF32(2)<<10,
// N=256: (N>>3)<<17, M=128: (M>>4)<<24
constexpr uint32_t IDESC_TF32 = (1u << 4) | (2u << 7) | (2u << 10) | (32u << 17) | (8u << 24);
#endif  // HAS_TCGEN05

// ---------------------------------------------------------------------------
// tcgen05 cg1 tf32 SS GEMM, CTA tile 256(M) x 256(N), BK=32, 3-stage ring.
// A [M,K] K-contiguous, B [N,K] K-contiguous: C = A * B^T.
// EPI: 0 = tf32-rounded tanh
//      1 = p = rna(exp(s/32-26)) masked + per-tile row sums
//      3 = out scaled by linv[row]; bn==0 CTAs also emit att = A*linv while
//          consuming A tiles (A = unnormalized p).
// ---------------------------------------------------------------------------
template <int EPI>
__global__ void __launch_bounds__(256, 1)
gemm_tc(const float* __restrict__ Ag, const float* __restrict__ Bg,
        float* __restrict__ Cg,
        int Kdim, int lda, int ldb, int ldc,
        size_t strA, size_t strB, size_t strC,
        const int* __restrict__ kli, int kn, float* __restrict__ partial,
        const float* __restrict__ linvp, float* __restrict__ attw)
{
#if HAS_TCGEN05
    extern __shared__ char smem[];
    const uint32_t su = smem_u32(smem);
    const int tid = threadIdx.x;
    const int wid = tid >> 5;
    const int lane = tid & 31;
    const int bn = blockIdx.x * 256;
    const int bm = blockIdx.y * 256;
    const int bz = blockIdx.z;

    const float* Ab = Ag + (size_t)bz * strA;
    const float* Bb = Bg + (size_t)bz * strB;
    float* Cb = Cg + (size_t)bz * strC;

    if (wid == 0) { tmem_alloc(su, 512); tmem_relinquish(); }
    if (tid == 0) {
        mbar_init(su + 8, 1);
        mbar_init(su + 16, 1);
        mbar_init(su + 24, 1);
    }
    __syncthreads();
    uint32_t tb;
    asm volatile("ld.shared.b32 %0, [%1];" : "=r"(tb) : "r"(su));

    const int NKT = Kdim >> 5;

    auto load_stage = [&](int kt, int s) {
        uint32_t abase = su + 1024 + s * STAGE_BYTES;
        uint32_t bbase = abase + 32768;
        const float* As = Ab + (size_t)bm * lda + kt * 32;
        const float* Bs = Bb + (size_t)bn * ldb + kt * 32;
        #pragma unroll
        for (int p = 0; p < 8; p++) {
            int idx = tid + p * 256;
            int row = idx >> 3, c16 = idx & 7;
            cp16(abase + swz(row * 128 + c16 * 16), As + (size_t)row * lda + c16 * 4);
        }
        #pragma unroll
        for (int p = 0; p < 8; p++) {
            int idx = tid + p * 256;
            int row = idx >> 3, c16 = idx & 7;
            cp16(bbase + swz(row * 128 + c16 * 16), Bs + (size_t)row * ldb + c16 * 4);
        }
    };

    int ph[STAGES] = {0, 0, 0};
    load_stage(0, 0); cp_commit();
    load_stage(1, 1); cp_commit();

    for (int kt = 0; kt < NKT; kt++) {
        int lb = (kt + 2) % 3;
        if (kt >= 1) {                       // buffer lb was consumed by stage kt-1
            mbar_wait(su + 8 + lb * 8, ph[lb]);
            ph[lb] ^= 1;
        }
        if (kt + 2 < NKT) load_stage(kt + 2, lb);
        cp_commit();
        cp_wait<2>();
        __syncthreads();                     // ALL threads' stage-kt data visible
        // att side-channel: bn==0 CTAs emit att rows from the resident p tile.
        // Runs after the barrier above (cross-thread cp.async visibility); the
        // extra barrier below orders these reads before the buffer's next refill.
        if (EPI == 3 && bn == 0) {
            char* ab = smem + 1024 + (kt % 3) * STAGE_BYTES;
            float lv = linvp[(size_t)bz * L + bm + tid];
            float* arow = attw + ((size_t)bz * L + bm + tid) * (size_t)L + kt * 32;
            #pragma unroll
            for (int c = 0; c < 8; c++) {
                float4 vv = *(float4*)(ab + swz((uint32_t)(tid * 128 + c * 16)));
                vv.x *= lv; vv.y *= lv; vv.z *= lv; vv.w *= lv;
                *(float4*)(arow + c * 4) = vv;
            }
        }
        if (EPI == 3) __syncthreads();       // att reads done before next refill
        if (wid == 0) {
            fence_async();
            if (elect_one()) {
                int s = kt % 3;
                uint32_t abase = su + 1024 + s * STAGE_BYTES;
                uint64_t ad = DESC_BASE_SW128 | ((abase >> 4) & 0x3FFF);
                uint64_t bd = DESC_BASE_SW128 | (((abase + 32768) >> 4) & 0x3FFF);
                #pragma unroll
                for (int k8 = 0; k8 < 4; k8++) {
                    uint32_t en = (kt > 0 || k8 > 0) ? 1u : 0u;
                    mma_tf32_ss(tb,       ad + k8 * 2,        bd + k8 * 2, IDESC_TF32, en);
                    mma_tf32_ss(tb + 256, ad + 1024 + k8 * 2, bd + k8 * 2, IDESC_TF32, en);
                }
                tc_commit(su + 8 + s * 8);
            }
        }
    }

    {
        int ls = (NKT - 1) % 3;
        mbar_wait(su + 8 + ls * 8, ph[ls]);
    }
    tc_fence_after();
    __syncthreads();

    // ---------------- epilogue: TMEM -> smem -> coalesced gmem ----------------
    float* stg = (float*)(smem + 1024);                 // 128 x 36 floats
    int* mk = (int*)(smem + 1024 + 128 * 36 * 4);       // 256 mask ints
    if (EPI == 1) mk[tid] = kli[(size_t)bz * kn + bn + tid];
    __syncthreads();

    float rs[2] = {0.f, 0.f};
    #pragma unroll 1
    for (int h = 0; h < 2; h++) {
        #pragma unroll 1
        for (int cb = 0; cb < 256; cb += 32) {
            if (wid < 4) {
                uint32_t r[32];
                LDTM32(r, tb + h * 256 + cb);
                tc_wait_ld();
                float lf = 1.f;
                if (EPI == 3)
                    lf = linvp[(size_t)bz * L + bm + h * 128 + wid * 32 + lane];
                float v[32];
                #pragma unroll
                for (int j = 0; j < 32; j++) {
                    float x = __uint_as_float(r[j]);
                    if (EPI == 0) {
                        v[j] = rna_tf32(tanhf(x));
                    } else if (EPI == 1) {
                        float m = (mk[cb + j] == 0) ? 0.f : 1.f;
                        v[j] = rna_tf32(m * __expf(x * 0.03125f - 26.f));
                        rs[h] += v[j];
                    } else {
                        v[j] = x * lf;
                    }
                }
                int row = wid * 32 + lane;
                #pragma unroll
                for (int j4 = 0; j4 < 8; j4++) {
                    *(float4*)&stg[row * 36 + j4 * 4] =
                        make_float4(v[j4 * 4], v[j4 * 4 + 1], v[j4 * 4 + 2], v[j4 * 4 + 3]);
                }
            }
            __syncthreads();
            #pragma unroll
            for (int p = 0; p < 4; p++) {
                int idx = tid + p * 256;
                int r2 = idx >> 3, c4 = idx & 7;
                float4 val = *(float4*)&stg[r2 * 36 + c4 * 4];
                *(float4*)&Cb[(size_t)(bm + h * 128 + r2) * ldc + bn + cb + c4 * 4] = val;
            }
            __syncthreads();
        }
    }

    if (EPI == 1 && wid < 4) {
        #pragma unroll
        for (int h = 0; h < 2; h++) {
            size_t row = (size_t)bz * L + bm + h * 128 + wid * 32 + lane;
            partial[row * NT_STRIDE + blockIdx.x] = rs[h];
        }
    }

    __syncthreads();
    if (wid == 0) tmem_dealloc(tb, 512);
#endif  // HAS_TCGEN05
}

// ---------------------------------------------------------------------------
// Fallback: mma.sync tf32, 128x128 tile (compute_103 builds only).
// ---------------------------------------------------------------------------
DEV_INLINE void mma_tf32_sync(float c[4], const uint32_t a[4], const uint32_t b[2]) {
    asm volatile(
        "mma.sync.aligned.m16n8k8.row.col.f32.tf32.tf32.f32 "
        "{%0,%1,%2,%3},{%4,%5,%6,%7},{%8,%9},{%0,%1,%2,%3};"
        : "+f"(c[0]), "+f"(c[1]), "+f"(c[2]), "+f"(c[3])
        : "r"(a[0]), "r"(a[1]), "r"(a[2]), "r"(a[3]), "r"(b[0]), "r"(b[1]));
}

template <int EPI>
__global__ void __launch_bounds__(256, 2)
gemm_fb(const float* __restrict__ Ag, const float* __restrict__ Bg,
        float* __restrict__ Cg,
        int Kdim, int lda, int ldb, int ldc,
        size_t strA, size_t strB, size_t strC,
        const int* __restrict__ kli, int kn, float* __restrict__ partial,
        const float* __restrict__ linvp, float* __restrict__ attw)
{
#if !HAS_TCGEN05
    extern __shared__ float sm[];
    constexpr int ASZ = 128 * 36;
    float* shA = sm;
    float* shB = sm + 2 * ASZ;

    const int tid  = threadIdx.x;
    const int lane = tid & 31;
    const int warp = tid >> 5;
    const int g = lane >> 2;
    const int t = lane & 3;
    const int wm = (warp >> 2) * 64;
    const int wn = (warp & 3) * 32;
    const int bm = blockIdx.y * 128;
    const int bn = blockIdx.x * 128;
    const int bz = blockIdx.z;

    const float* Ab = Ag + (size_t)bz * strA;
    const float* Bb = Bg + (size_t)bz * strB;
    float* Cb = Cg + (size_t)bz * strC;

    float acc[4][4][4];
    #pragma unroll
    for (int mi = 0; mi < 4; mi++)
        #pragma unroll
        for (int ni = 0; ni < 4; ni++)
            #pragma unroll
            for (int e = 0; e < 4; e++) acc[mi][ni][e] = 0.f;

    const int nkt = Kdim >> 5;

    auto load_stage = [&](int kt, int buf) {
        float* dA = shA + buf * ASZ;
        float* dB = shB + buf * ASZ;
        const float* sA = Ab + (size_t)bm * lda + kt * 32;
        const float* sB = Bb + (size_t)bn * ldb + kt * 32;
        #pragma unroll
        for (int p = 0; p < 4; p++) {
            int e = tid + p * 256;
            int r = e >> 3, q4 = (e & 7) << 2;
            cp16p(dA + r * 36 + q4, sA + (size_t)r * lda + q4);
        }
        #pragma unroll
        for (int p = 0; p < 4; p++) {
            int e = tid + p * 256;
            int r = e >> 3, q4 = (e & 7) << 2;
            cp16p(dB + r * 36 + q4, sB + (size_t)r * ldb + q4);
        }
    };

    auto compute = [&](int buf) {
        const uint32_t* a0 = (const uint32_t*)(shA + buf * ASZ);
        const uint32_t* b0 = (const uint32_t*)(shB + buf * ASZ);
        #pragma unroll
        for (int kk = 0; kk < 4; ++kk) {
            const int c = kk * 8 + t;
            uint32_t af[4][4];
            #pragma unroll
            for (int mi = 0; mi < 4; mi++) {
                const int r = wm + mi * 16 + g;
                af[mi][0] = a0[r * 36 + c];
                af[mi][1] = a0[(r + 8) * 36 + c];
                af[mi][2] = a0[r * 36 + c + 4];
                af[mi][3] = a0[(r + 8) * 36 + c + 4];
            }
            uint32_t bf[4][2];
            #pragma unroll
            for (int ni = 0; ni < 4; ni++) {
                const int n = wn + ni * 8 + g;
                bf[ni][0] = b0[n * 36 + c];
                bf[ni][1] = b0[n * 36 + c + 4];
            }
            #pragma unroll
            for (int mi = 0; mi < 4; mi++)
                #pragma unroll
                for (int ni = 0; ni < 4; ni++)
                    mma_tf32_sync(acc[mi][ni], af[mi], bf[ni]);
        }
    };

    load_stage(0, 0);
    cp_commit();
    for (int kt = 0; kt < nkt; ++kt) {
        int buf = kt & 1;
        if (kt + 1 < nkt) {
            load_stage(kt + 1, buf ^ 1);
            cp_commit();
            cp_wait<1>();
        } else {
            cp_wait<0>();
        }
        __syncthreads();
        if (EPI == 3 && bn == 0) {
            int row = tid >> 1, half = (tid & 1) * 16;
            const float* dA = shA + buf * ASZ;
            float lv = linvp[(size_t)bz * L + bm + row];
            float* arow = attw + ((size_t)bz * L + bm + row) * (size_t)L + kt * 32 + half;
            #pragma unroll
            for (int c = 0; c < 4; c++) {
                float4 vv = *(float4*)&dA[row * 36 + half + c * 4];
                vv.x *= lv; vv.y *= lv; vv.z *= lv; vv.w *= lv;
                *(float4*)(arow + c * 4) = vv;
            }
        }
        compute(buf);
        __syncthreads();
    }

    if (EPI == 0 || EPI == 3) {
        #pragma unroll
        for (int mi = 0; mi < 4; mi++) {
            const int r0 = bm + wm + mi * 16 + g;
            float lfa = 1.f, lfb = 1.f;
            if (EPI == 3) {
                lfa = linvp[(size_t)bz * L + r0];
                lfb = linvp[(size_t)bz * L + r0 + 8];
            }
            #pragma unroll
            for (int ni = 0; ni < 4; ni++) {
                const int cl = bn + wn + ni * 8 + 2 * t;
                float2 v0, v1;
                if (EPI == 0) {
                    v0.x = rna_tf32(tanhf(acc[mi][ni][0]));
                    v0.y = rna_tf32(tanhf(acc[mi][ni][1]));
                    v1.x = rna_tf32(tanhf(acc[mi][ni][2]));
                    v1.y = rna_tf32(tanhf(acc[mi][ni][3]));
                } else {
                    v0.x = acc[mi][ni][0] * lfa; v0.y = acc[mi][ni][1] * lfa;
                    v1.x = acc[mi][ni][2] * lfb; v1.y = acc[mi][ni][3] * lfb;
                }
                *(float2*)(Cb + (size_t)r0 * ldc + cl) = v0;
                *(float2*)(Cb + (size_t)(r0 + 8) * ldc + cl) = v1;
            }
        }
    } else {
        int* mk = (int*)sm;
        float* red = sm + 128;
        if (tid < 128) mk[tid] = kli[(size_t)bz * kn + bn + tid];
        __syncthreads();

        float rsv[4][2];
        #pragma unroll
        for (int mi = 0; mi < 4; mi++) { rsv[mi][0] = 0.f; rsv[mi][1] = 0.f; }

        #pragma unroll
        for (int mi = 0; mi < 4; mi++) {
            const int r0 = bm + wm + mi * 16 + g;
            #pragma unroll
            for (int ni = 0; ni < 4; ni++) {
                const int cl = wn + ni * 8 + 2 * t;
                const float m0 = (mk[cl] == 0) ? 0.f : 1.f;
                const float m1 = (mk[cl + 1] == 0) ? 0.f : 1.f;
                float p00 = rna_tf32(m0 * __expf(acc[mi][ni][0] * 0.03125f - 26.f));
                float p01 = rna_tf32(m1 * __expf(acc[mi][ni][1] * 0.03125f - 26.f));
                float p10 = rna_tf32(m0 * __expf(acc[mi][ni][2] * 0.03125f - 26.f));
                float p11 = rna_tf32(m1 * __expf(acc[mi][ni][3] * 0.03125f - 26.f));
                float2 v0 = {p00, p01}, v1 = {p10, p11};
                *(float2*)(Cb + (size_t)r0 * ldc + bn + cl) = v0;
                *(float2*)(Cb + (size_t)(r0 + 8) * ldc + bn + cl) = v1;
                rsv[mi][0] += p00 + p01;
                rsv[mi][1] += p10 + p11;
            }
        }
        #pragma unroll
        for (int mi = 0; mi < 4; mi++) {
            #pragma unroll
            for (int h = 0; h < 2; h++) {
                float vsum = rsv[mi][h];
                vsum += __shfl_xor_sync(0xffffffffu, vsum, 1);
                vsum += __shfl_xor_sync(0xffffffffu, vsum, 2);
                if (t == 0)
                    red[(warp & 3) * 128 + wm + mi * 16 + g + h * 8] = vsum;
            }
        }
        __syncthreads();
        if (tid < 128) {
            float tot = red[tid] + red[128 + tid] + red[256 + tid] + red[384 + tid];
            partial[(size_t)(bz * L + bm + tid) * NT_STRIDE + blockIdx.x] = tot;
        }
    }
#endif  // !HAS_TCGEN05
}

// ---------------- aux kernels (path-agnostic) ----------------
__global__ void round3_kernel(const float4* __restrict__ q, const float4* __restrict__ k,
                              const float4* __restrict__ w,
                              float4* __restrict__ qr, float4* __restrict__ kr,
                              float4* __restrict__ wr) {
    const size_t nqk = (size_t)BATCH * L * D / 4;
    size_t i = (size_t)blockIdx.x * 256 + threadIdx.x;
    const float4* src;
    float4* dst;
    size_t j;
    if (i < nqk)            { src = q; dst = qr; j = i; }
    else if (i < 2 * nqk)   { src = k; dst = kr; j = i - nqk; }
    else                    { src = w; dst = wr; j = i - 2 * nqk; }
    float4 v = src[j];
    v.x = rna_tf32(v.x); v.y = rna_tf32(v.y); v.z = rna_tf32(v.z); v.w = rna_tf32(v.w);
    dst[j] = v;
}

__global__ void transpose_round_kernel(const float* __restrict__ V, float* __restrict__ VT) {
    __shared__ float t[32][33];
    int b = blockIdx.z;
    int l0 = blockIdx.x * 32, d0 = blockIdx.y * 32;
    int tx = threadIdx.x, ty = threadIdx.y;
    const float* Vb = V + (size_t)b * L * D;
    float* Tb = VT + (size_t)b * D * L;
    #pragma unroll
    for (int i = 0; i < 32; i += 8)
        t[ty + i][tx] = Vb[(size_t)(l0 + ty + i) * D + d0 + tx];
    __syncthreads();
    #pragma unroll
    for (int i = 0; i < 32; i += 8)
        Tb[(size_t)(d0 + ty + i) * L + l0 + tx] = rna_tf32(t[tx][ty + i]);
}

__global__ void reduce_l_kernel(const float* __restrict__ partial, float* __restrict__ linv) {
    int i = blockIdx.x * 256 + threadIdx.x;
    float s = 0.f;
    #pragma unroll
    for (int tIdx = 0; tIdx < NT_STRIDE; tIdx++) s += partial[(size_t)i * NT_STRIDE + tIdx];
    linv[i] = (s > 0.f) ? (1.0f / s) : 0.f;
}

extern "C" void kernel_launch(void* const* d_in, const int* in_sizes, int n_in,
                              void* d_out, int out_size)
{
    const float* dq   = (const float*)d_in[0];
    const float* dk   = (const float*)d_in[1];
    const float* dv   = (const float*)d_in[2];
    const int*   dkli = (const int*)d_in[3];
    const float* dW   = (const float*)d_in[4];
    float* d_o   = (float*)d_out;
    float* d_att = d_o + (size_t)BATCH * L * D;

    float *pKT, *pVT, *pQr, *pKr, *pWr, *pP, *pPart, *pLinv;
    cudaGetSymbolAddress((void**)&pKT,   g_KT);
    cudaGetSymbolAddress((void**)&pVT,   g_VT);
    cudaGetSymbolAddress((void**)&pQr,   g_Qr);
    cudaGetSymbolAddress((void**)&pKr,   g_Kr);
    cudaGetSymbolAddress((void**)&pWr,   g_Wr);
    cudaGetSymbolAddress((void**)&pP,    g_P);
    cudaGetSymbolAddress((void**)&pPart, g_partial);
    cudaGetSymbolAddress((void**)&pLinv, g_linv);

    cudaFuncSetAttribute(gemm_tc<0>, cudaFuncAttributeMaxDynamicSharedMemorySize, SMEM_TC);
    cudaFuncSetAttribute(gemm_tc<1>, cudaFuncAttributeMaxDynamicSharedMemorySize, SMEM_TC);
    cudaFuncSetAttribute(gemm_tc<3>, cudaFuncAttributeMaxDynamicSharedMemorySize, SMEM_TC);
    cudaFuncSetAttribute(gemm_fb<0>, cudaFuncAttributeMaxDynamicSharedMemorySize, SMEM_FB);
    cudaFuncSetAttribute(gemm_fb<1>, cudaFuncAttributeMaxDynamicSharedMemorySize, SMEM_FB);
    cudaFuncSetAttribute(gemm_fb<3>, cudaFuncAttributeMaxDynamicSharedMemorySize, SMEM_FB);

    const size_t nqk4 = (size_t)BATCH * L * D / 4;
    const size_t nw4  = (size_t)D * D / 4;

    // 0) round Q, K, W to tf32 (one fused pass); VT = round(V^T)
    round3_kernel<<<(int)((2 * nqk4 + nw4) / 256), 256>>>(
        (const float4*)dq, (const float4*)dk, (const float4*)dW,
        (float4*)pQr, (float4*)pKr, (float4*)pWr);
    transpose_round_kernel<<<dim3(L / 32, D / 32, BATCH), dim3(32, 8)>>>(dv, pVT);

    // 1) KT = round(tanh(K @ W^T))  — one of tc/fb does work per compiled arch
    gemm_fb<0><<<dim3(D / 128, L / 128, BATCH), 256, SMEM_FB>>>(
        pKr, pWr, pKT, D, D, D, D, (size_t)L * D, 0, (size_t)L * D,
        nullptr, 0, nullptr, nullptr, nullptr);
    gemm_tc<0><<<dim3(D / 256, L / 256, BATCH), 256, SMEM_TC>>>(
        pKr, pWr, pKT, D, D, D, D, (size_t)L * D, 0, (size_t)L * D,
        nullptr, 0, nullptr, nullptr, nullptr);

    // 2) p = rna(exp(Q.KT^T/32 - 26)) masked + per-tile row sums -> g_P
    gemm_fb<1><<<dim3(L / 128, L / 128, BATCH), 256, SMEM_FB>>>(
        pQr, pKT, pP, D, D, D, L,
        (size_t)L * D, (size_t)L * D, (size_t)L * L, dkli, L, pPart, nullptr, nullptr);
    gemm_tc<1><<<dim3(L / 256, L / 256, BATCH), 256, SMEM_TC>>>(
        pQr, pKT, pP, D, D, D, L,
        (size_t)L * D, (size_t)L * D, (size_t)L * L, dkli, L, pPart, nullptr, nullptr);

    // 3) linv = 1 / row sums
    reduce_l_kernel<<<BATCH * L / 256, 256>>>(pPart, pLinv);

    // 4) out = linv ⊙ (p @ V); att = p * linv emitted by bn==0 CTAs
    gemm_fb<3><<<dim3(D / 128, L / 128, BATCH), 256, SMEM_FB>>>(
        pP, pVT, d_o, L, L, L, D,
        (size_t)L * L, (size_t)L * D, (size_t)L * D, nullptr, 0, nullptr, pLinv, d_att);
    gemm_tc<3><<<dim3(D / 256, L / 256, BATCH), 256, SMEM_TC>>>(
        pP, pVT, d_o, L, L, L, D,
        (size_t)L * L, (size_t)L * D, (size_t)L * D, nullptr, 0, nullptr, pLinv, d_att);
}

// round 10
// speedup vs baseline: 1.3440x; 1.3440x over previous
#include <cuda_runtime.h>
#include <cstdint>

#define DEV_INLINE __device__ __forceinline__

#if defined(__CUDA_ARCH__) && defined(__CUDA_ARCH_FEAT_SM103_ALL)
#define HAS_TCGEN05 1
#else
#define HAS_TCGEN05 0
#endif

constexpr int BATCH = 16;
constexpr int L = 2048;
constexpr int D = 1024;
constexpr int NT_STRIDE = 16;       // partial-sum slots per row
constexpr int STAGES = 3;
constexpr int STAGE_BYTES = 65536;  // 32KB A + 32KB B
constexpr int SMEM_TC = 1024 + STAGES * STAGE_BYTES;      // 197632
constexpr int SMEM_FB = (4 * 128 * 36) * 4;               // 73728

// ---- scratch (static: no cudaMalloc allowed) ----
__device__ float g_KT[(size_t)BATCH * L * D];
__device__ float g_VT[(size_t)BATCH * D * L];
__device__ float g_Qr[(size_t)BATCH * L * D];
__device__ float g_Kr[(size_t)BATCH * L * D];
__device__ float g_Wr[(size_t)D * D];
__device__ float g_partial[(size_t)BATCH * L * NT_STRIDE];  // zero-init
__device__ float g_linv[(size_t)BATCH * L];

// ---------------- common helpers ----------------
DEV_INLINE uint32_t f2tf(float f) {
    uint32_t u;
    asm("cvt.rna.tf32.f32 %0, %1;" : "=r"(u) : "f"(f));
    return u;
}
DEV_INLINE float rna_tf32(float f) { return __uint_as_float(f2tf(f)); }

DEV_INLINE uint32_t smem_u32(const void* p) {
    uint32_t a;
    asm("{ .reg .u64 t; cvta.to.shared.u64 t, %1; cvt.u32.u64 %0, t; }" : "=r"(a) : "l"(p));
    return a;
}
DEV_INLINE void cp16(uint32_t s, const float* g) {
    asm volatile("cp.async.cg.shared.global [%0], [%1], 16;" :: "r"(s), "l"(g));
}
DEV_INLINE void cp16p(float* s, const float* g) {
    uint32_t sa = (uint32_t)__cvta_generic_to_shared(s);
    asm volatile("cp.async.cg.shared.global [%0], [%1], 16;" :: "r"(sa), "l"(g));
}
DEV_INLINE void cp_commit() { asm volatile("cp.async.commit_group;" ::: "memory"); }
template <int N> DEV_INLINE void cp_wait() {
    asm volatile("cp.async.wait_group %0;" :: "n"(N) : "memory");
}
DEV_INLINE uint32_t swz(uint32_t o) { return o ^ ((o >> 3) & 0x70); }

// =====================================================================
// tcgen05 cg1 path (only materialized for compute_103a)
// =====================================================================
#if HAS_TCGEN05
DEV_INLINE uint32_t elect_one() {
    uint32_t p;
    asm volatile("{ .reg .pred P; elect.sync _|P, 0xFFFFFFFF; selp.b32 %0, 1, 0, P; }" : "=r"(p));
    return p;
}
DEV_INLINE void mbar_init(uint32_t m, uint32_t cnt) {
    asm volatile("mbarrier.init.shared.b64 [%0], %1;" :: "r"(m), "r"(cnt) : "memory");
}
DEV_INLINE void mbar_wait(uint32_t m, uint32_t parity) {
    asm volatile(
        "{\n\t.reg .pred P;\n\t"
        "WL%=:\n\t"
        "mbarrier.try_wait.parity.acquire.cta.shared::cta.b64 P, [%0], %1, 0x989680;\n\t"
        "@P bra.uni WD%=;\n\t"
        "bra.uni WL%=;\n\t"
        "WD%=:\n\t}"
        :: "r"(m), "r"(parity) : "memory");
}
DEV_INLINE void mbar_arrive_rel(uint32_t m) {
    asm volatile("mbarrier.arrive.release.cta.shared::cta.b64 _, [%0];"
                 :: "r"(m) : "memory");
}
DEV_INLINE void tmem_alloc(uint32_t smem_dst, uint32_t ncols) {
    asm volatile("tcgen05.alloc.cta_group::1.sync.aligned.shared::cta.b32 [%0], %1;"
                 :: "r"(smem_dst), "r"(ncols) : "memory");
}
DEV_INLINE void tmem_dealloc(uint32_t tmem, uint32_t ncols) {
    asm volatile("tcgen05.dealloc.cta_group::1.sync.aligned.b32 %0, %1;" :: "r"(tmem), "r"(ncols));
}
DEV_INLINE void tmem_relinquish() {
    asm volatile("tcgen05.relinquish_alloc_permit.cta_group::1.sync.aligned;");
}
DEV_INLINE void mma_tf32_ss(uint32_t d, uint64_t a, uint64_t b, uint32_t idesc, uint32_t en) {
    asm volatile(
        "{\n\t.reg .pred p;\n\t"
        "setp.ne.u32 p, %5, 0;\n\t"
        "tcgen05.mma.cta_group::1.kind::tf32 [%0], %1, %2, %3, {%4,%4,%4,%4}, p;\n\t}"
        :: "r"(d), "l"(a), "l"(b), "r"(idesc), "r"(0u), "r"(en) : "memory");
}
DEV_INLINE void tc_commit(uint32_t mbar) {
    asm volatile("tcgen05.commit.cta_group::1.mbarrier::arrive::one.shared::cluster.b64 [%0];"
                 :: "r"(mbar) : "memory");
}
DEV_INLINE void fence_async() { asm volatile("fence.proxy.async.shared::cta;" ::: "memory"); }
DEV_INLINE void tc_fence_after() { asm volatile("tcgen05.fence::after_thread_sync;" ::: "memory"); }
DEV_INLINE void tc_wait_ld() { asm volatile("tcgen05.wait::ld.sync.aligned;" ::: "memory"); }

#define LDTM32(r, addr)                                                        \
    asm volatile("tcgen05.ld.sync.aligned.32x32b.x32.b32 "                      \
        "{%0,%1,%2,%3,%4,%5,%6,%7,%8,%9,%10,%11,%12,%13,%14,%15,"               \
        "%16,%17,%18,%19,%20,%21,%22,%23,%24,%25,%26,%27,%28,%29,%30,%31}, [%32];" \
        : "=r"((r)[0]), "=r"((r)[1]), "=r"((r)[2]), "=r"((r)[3]),               \
          "=r"((r)[4]), "=r"((r)[5]), "=r"((r)[6]), "=r"((r)[7]),               \
          "=r"((r)[8]), "=r"((r)[9]), "=r"((r)[10]), "=r"((r)[11]),             \
          "=r"((r)[12]), "=r"((r)[13]), "=r"((r)[14]), "=r"((r)[15]),           \
          "=r"((r)[16]), "=r"((r)[17]), "=r"((r)[18]), "=r"((r)[19]),           \
          "=r"((r)[20]), "=r"((r)[21]), "=r"((r)[22]), "=r"((r)[23]),           \
          "=r"((r)[24]), "=r"((r)[25]), "=r"((r)[26]), "=r"((r)[27]),           \
          "=r"((r)[28]), "=r"((r)[29]), "=r"((r)[30]), "=r"((r)[31])            \
        : "r"(addr))

constexpr uint64_t DESC_BASE_SW128 =
    (2ULL << 61) | (1ULL << 46) | (64ULL << 32) | (1ULL << 16);
// idesc kind::tf32: dtype=F32(1)<<4, atype=TF32(2)<<7, btype=TF32(2)<<10,
// N=256: (N>>3)<<17, M=128: (M>>4)<<24
constexpr uint32_t IDESC_TF32 = (1u << 4) | (2u << 7) | (2u << 10) | (32u << 17) | (8u << 24);
#endif  // HAS_TCGEN05

// ---------------------------------------------------------------------------
// tcgen05 cg1 tf32 SS GEMM, 256x256 CTA tile, BK=32, 3-stage ring.
// Warp-specialized mbarrier pipeline (no per-iteration __syncthreads):
//   producers (all 8 warps): cp.async ring, arrive full[s] (count 8),
//   recycle buffers via empty[s] (armed by tcgen05.commit).
//   MMA (elected thread of warp 0): wait full[s] -> 8 dispatches -> commit.
// EPI: 0 = tf32-rounded tanh, 1 = p=exp(s/32-26) masked + row sums, 2 = identity
// ---------------------------------------------------------------------------
template <int EPI>
__global__ void __launch_bounds__(256, 1)
gemm_tc(const float* __restrict__ Ag, const float* __restrict__ Bg,
        float* __restrict__ Cg,
        int Kdim, int lda, int ldb, int ldc,
        size_t strA, size_t strB, size_t strC,
        const int* __restrict__ kli, int kn, float* __restrict__ partial)
{
#if HAS_TCGEN05
    extern __shared__ char smem[];
    const uint32_t su = smem_u32(smem);
    const int tid = threadIdx.x;
    const int wid = tid >> 5;
    const int lane = tid & 31;
    const int bn = blockIdx.x * 256;
    const int bm = blockIdx.y * 256;
    const int bz = blockIdx.z;

    const uint32_t FULL = su + 8;     // full[i] = FULL + 8*i   (count 8)
    const uint32_t EMPT = su + 32;    // empty[i] = EMPT + 8*i  (count 1)
    const uint32_t DONE = su + 56;    // done            (count 1)

    const float* Ab = Ag + (size_t)bz * strA;
    const float* Bb = Bg + (size_t)bz * strB;
    float* Cb = Cg + (size_t)bz * strC;

    if (wid == 0) { tmem_alloc(su, 512); tmem_relinquish(); }
    if (tid == 0) {
        #pragma unroll
        for (int i = 0; i < STAGES; i++) {
            mbar_init(FULL + i * 8, 8);
            mbar_init(EMPT + i * 8, 1);
        }
        mbar_init(DONE, 1);
    }
    __syncthreads();
    uint32_t tb;
    asm volatile("ld.shared.b32 %0, [%1];" : "=r"(tb) : "r"(su));

    const int NKT = Kdim >> 5;

    auto load_stage = [&](int kt, int s) {
        uint32_t abase = su + 1024 + s * STAGE_BYTES;
        uint32_t bbase = abase + 32768;
        const float* As = Ab + (size_t)bm * lda + kt * 32;
        const float* Bs = Bb + (size_t)bn * ldb + kt * 32;
        #pragma unroll
        for (int p = 0; p < 8; p++) {
            int idx = tid + p * 256;
            int row = idx >> 3, c16 = idx & 7;
            cp16(abase + swz(row * 128 + c16 * 16), As + (size_t)row * lda + c16 * 4);
        }
        #pragma unroll
        for (int p = 0; p < 8; p++) {
            int idx = tid + p * 256;
            int row = idx >> 3, c16 = idx & 7;
            cp16(bbase + swz(row * 128 + c16 * 16), Bs + (size_t)row * ldb + c16 * 4);
        }
    };

    uint32_t ecp = 0;             // per-buffer empty parities (bits 0..2)
    uint32_t pf  = 0;             // per-buffer full parities (MMA thread)
    load_stage(0, 0); cp_commit();
    load_stage(1, 1); cp_commit();

    for (int kt = 0; kt < NKT; kt++) {
        const int s = kt % 3;
        // --- stage kt ready: publish to MMA ---
        cp_wait<1>();             // my lanes' stage-kt group retired
        __syncwarp();
        if (lane == 0) mbar_arrive_rel(FULL + s * 8);
        // --- MMA dispatch (elected thread of warp 0) ---
        if (wid == 0) {
            if (elect_one()) {
                mbar_wait(FULL + s * 8, (pf >> s) & 1);
                fence_async();
                uint32_t abase = su + 1024 + s * STAGE_BYTES;
                uint64_t ad = DESC_BASE_SW128 | ((abase >> 4) & 0x3FFF);
                uint64_t bd = DESC_BASE_SW128 | (((abase + 32768) >> 4) & 0x3FFF);
                #pragma unroll
                for (int k8 = 0; k8 < 4; k8++) {
                    uint32_t en = (kt > 0 || k8 > 0) ? 1u : 0u;
                    mma_tf32_ss(tb,       ad + k8 * 2,        bd + k8 * 2, IDESC_TF32, en);
                    mma_tf32_ss(tb + 256, ad + 1024 + k8 * 2, bd + k8 * 2, IDESC_TF32, en);
                }
                tc_commit(EMPT + s * 8);
            }
            pf ^= 1u << s;        // warp-uniform parity update
        }
        // --- prefetch stage kt+2 ---
        if (kt + 2 < NKT) {
            const int nb = (kt + 2) % 3;
            if (kt >= 1) {        // buffer nb consumed by MMA(kt-1)
                mbar_wait(EMPT + nb * 8, (ecp >> nb) & 1);
                ecp ^= 1u << nb;
            }
            load_stage(kt + 2, nb);
        }
        cp_commit();
    }

    // drain: commit with no new MMAs waits for ALL prior MMAs
    if (wid == 0 && elect_one()) tc_commit(DONE);
    mbar_wait(DONE, 0);
    tc_fence_after();
    __syncthreads();

    // ---------------- epilogue: TMEM -> smem -> coalesced gmem ----------------
    float* stg = (float*)(smem + 1024);                 // 128 x 36 floats
    int* mk = (int*)(smem + 1024 + 128 * 36 * 4);       // 256 mask ints
    if (EPI == 1) mk[tid] = kli[(size_t)bz * kn + bn + tid];
    __syncthreads();

    float rs[2] = {0.f, 0.f};
    #pragma unroll 1
    for (int h = 0; h < 2; h++) {
        #pragma unroll 1
        for (int cb = 0; cb < 256; cb += 32) {
            if (wid < 4) {
                uint32_t r[32];
                LDTM32(r, tb + h * 256 + cb);
                tc_wait_ld();
                float v[32];
                #pragma unroll
                for (int j = 0; j < 32; j++) {
                    float x = __uint_as_float(r[j]);
                    if (EPI == 0) {
                        v[j] = rna_tf32(tanhf(x));
                    } else if (EPI == 1) {
                        float m = (mk[cb + j] == 0) ? 0.f : 1.f;
                        v[j] = m * __expf(x * 0.03125f - 26.f);
                        rs[h] += v[j];
                    } else {
                        v[j] = x;
                    }
                }
                int row = wid * 32 + lane;
                #pragma unroll
                for (int j4 = 0; j4 < 8; j4++) {
                    *(float4*)&stg[row * 36 + j4 * 4] =
                        make_float4(v[j4 * 4], v[j4 * 4 + 1], v[j4 * 4 + 2], v[j4 * 4 + 3]);
                }
            }
            __syncthreads();
            #pragma unroll
            for (int p = 0; p < 4; p++) {
                int idx = tid + p * 256;
                int r2 = idx >> 3, c4 = idx & 7;
                float4 val = *(float4*)&stg[r2 * 36 + c4 * 4];
                *(float4*)&Cb[(size_t)(bm + h * 128 + r2) * ldc + bn + cb + c4 * 4] = val;
            }
            __syncthreads();
        }
    }

    if (EPI == 1 && wid < 4) {
        #pragma unroll
        for (int h = 0; h < 2; h++) {
            size_t row = (size_t)bz * L + bm + h * 128 + wid * 32 + lane;
            partial[row * NT_STRIDE + blockIdx.x] = rs[h];
        }
    }

    __syncthreads();
    if (wid == 0) tmem_dealloc(tb, 512);
#endif  // HAS_TCGEN05
}

// ---------------------------------------------------------------------------
// Fallback: mma.sync tf32, 128x128 tile (compute_103 builds only).
// ---------------------------------------------------------------------------
DEV_INLINE void mma_tf32_sync(float c[4], const uint32_t a[4], const uint32_t b[2]) {
    asm volatile(
        "mma.sync.aligned.m16n8k8.row.col.f32.tf32.tf32.f32 "
        "{%0,%1,%2,%3},{%4,%5,%6,%7},{%8,%9},{%0,%1,%2,%3};"
        : "+f"(c[0]), "+f"(c[1]), "+f"(c[2]), "+f"(c[3])
        : "r"(a[0]), "r"(a[1]), "r"(a[2]), "r"(a[3]), "r"(b[0]), "r"(b[1]));
}

template <int EPI>
__global__ void __launch_bounds__(256, 2)
gemm_fb(const float* __restrict__ Ag, const float* __restrict__ Bg,
        float* __restrict__ Cg,
        int Kdim, int lda, int ldb, int ldc,
        size_t strA, size_t strB, size_t strC,
        const int* __restrict__ kli, int kn, float* __restrict__ partial)
{
#if !HAS_TCGEN05
    extern __shared__ float sm[];
    constexpr int ASZ = 128 * 36;
    float* shA = sm;
    float* shB = sm + 2 * ASZ;

    const int tid  = threadIdx.x;
    const int lane = tid & 31;
    const int warp = tid >> 5;
    const int g = lane >> 2;
    const int t = lane & 3;
    const int wm = (warp >> 2) * 64;
    const int wn = (warp & 3) * 32;
    const int bm = blockIdx.y * 128;
    const int bn = blockIdx.x * 128;
    const int bz = blockIdx.z;

    const float* Ab = Ag + (size_t)bz * strA;
    const float* Bb = Bg + (size_t)bz * strB;
    float* Cb = Cg + (size_t)bz * strC;

    float acc[4][4][4];
    #pragma unroll
    for (int mi = 0; mi < 4; mi++)
        #pragma unroll
        for (int ni = 0; ni < 4; ni++)
            #pragma unroll
            for (int e = 0; e < 4; e++) acc[mi][ni][e] = 0.f;

    const int nkt = Kdim >> 5;

    auto load_stage = [&](int kt, int buf) {
        float* dA = shA + buf * ASZ;
        float* dB = shB + buf * ASZ;
        const float* sA = Ab + (size_t)bm * lda + kt * 32;
        const float* sB = Bb + (size_t)bn * ldb + kt * 32;
        #pragma unroll
        for (int p = 0; p < 4; p++) {
            int e = tid + p * 256;
            int r = e >> 3, q4 = (e & 7) << 2;
            cp16p(dA + r * 36 + q4, sA + (size_t)r * lda + q4);
        }
        #pragma unroll
        for (int p = 0; p < 4; p++) {
            int e = tid + p * 256;
            int r = e >> 3, q4 = (e & 7) << 2;
            cp16p(dB + r * 36 + q4, sB + (size_t)r * ldb + q4);
        }
    };

    auto compute = [&](int buf) {
        const uint32_t* a0 = (const uint32_t*)(shA + buf * ASZ);
        const uint32_t* b0 = (const uint32_t*)(shB + buf * ASZ);
        #pragma unroll
        for (int kk = 0; kk < 4; ++kk) {
            const int c = kk * 8 + t;
            uint32_t af[4][4];
            #pragma unroll
            for (int mi = 0; mi < 4; mi++) {
                const int r = wm + mi * 16 + g;
                af[mi][0] = a0[r * 36 + c];
                af[mi][1] = a0[(r + 8) * 36 + c];
                af[mi][2] = a0[r * 36 + c + 4];
                af[mi][3] = a0[(r + 8) * 36 + c + 4];
            }
            uint32_t bf[4][2];
            #pragma unroll
            for (int ni = 0; ni < 4; ni++) {
                const int n = wn + ni * 8 + g;
                bf[ni][0] = b0[n * 36 + c];
                bf[ni][1] = b0[n * 36 + c + 4];
            }
            #pragma unroll
            for (int mi = 0; mi < 4; mi++)
                #pragma unroll
                for (int ni = 0; ni < 4; ni++)
                    mma_tf32_sync(acc[mi][ni], af[mi], bf[ni]);
        }
    };

    load_stage(0, 0);
    cp_commit();
    for (int kt = 0; kt < nkt; ++kt) {
        int buf = kt & 1;
        if (kt + 1 < nkt) {
            load_stage(kt + 1, buf ^ 1);
            cp_commit();
            cp_wait<1>();
        } else {
            cp_wait<0>();
        }
        __syncthreads();
        compute(buf);
        __syncthreads();
    }

    if (EPI == 0 || EPI == 2) {
        #pragma unroll
        for (int mi = 0; mi < 4; mi++) {
            const int r0 = bm + wm + mi * 16 + g;
            #pragma unroll
            for (int ni = 0; ni < 4; ni++) {
                const int cl = bn + wn + ni * 8 + 2 * t;
                float2 v0, v1;
                if (EPI == 0) {
                    v0.x = rna_tf32(tanhf(acc[mi][ni][0]));
                    v0.y = rna_tf32(tanhf(acc[mi][ni][1]));
                    v1.x = rna_tf32(tanhf(acc[mi][ni][2]));
                    v1.y = rna_tf32(tanhf(acc[mi][ni][3]));
                } else {
                    v0.x = acc[mi][ni][0]; v0.y = acc[mi][ni][1];
                    v1.x = acc[mi][ni][2]; v1.y = acc[mi][ni][3];
                }
                *(float2*)(Cb + (size_t)r0 * ldc + cl) = v0;
                *(float2*)(Cb + (size_t)(r0 + 8) * ldc + cl) = v1;
            }
        }
    } else {
        int* mk = (int*)sm;
        float* red = sm + 128;
        if (tid < 128) mk[tid] = kli[(size_t)bz * kn + bn + tid];
        __syncthreads();

        float rsv[4][2];
        #pragma unroll
        for (int mi = 0; mi < 4; mi++) { rsv[mi][0] = 0.f; rsv[mi][1] = 0.f; }

        #pragma unroll
        for (int mi = 0; mi < 4; mi++) {
            const int r0 = bm + wm + mi * 16 + g;
            #pragma unroll
            for (int ni = 0; ni < 4; ni++) {
                const int cl = wn + ni * 8 + 2 * t;
                const float m0 = (mk[cl] == 0) ? 0.f : 1.f;
                const float m1 = (mk[cl + 1] == 0) ? 0.f : 1.f;
                float p00 = m0 * __expf(acc[mi][ni][0] * 0.03125f - 26.f);
                float p01 = m1 * __expf(acc[mi][ni][1] * 0.03125f - 26.f);
                float p10 = m0 * __expf(acc[mi][ni][2] * 0.03125f - 26.f);
                float p11 = m1 * __expf(acc[mi][ni][3] * 0.03125f - 26.f);
                float2 v0 = {p00, p01}, v1 = {p10, p11};
                *(float2*)(Cb + (size_t)r0 * ldc + bn + cl) = v0;
                *(float2*)(Cb + (size_t)(r0 + 8) * ldc + bn + cl) = v1;
                rsv[mi][0] += p00 + p01;
                rsv[mi][1] += p10 + p11;
            }
        }
        #pragma unroll
        for (int mi = 0; mi < 4; mi++) {
            #pragma unroll
            for (int h = 0; h < 2; h++) {
                float vsum = rsv[mi][h];
                vsum += __shfl_xor_sync(0xffffffffu, vsum, 1);
                vsum += __shfl_xor_sync(0xffffffffu, vsum, 2);
                if (t == 0)
                    red[(warp & 3) * 128 + wm + mi * 16 + g + h * 8] = vsum;
            }
        }
        __syncthreads();
        if (tid < 128) {
            float tot = red[tid] + red[128 + tid] + red[256 + tid] + red[384 + tid];
            partial[(size_t)(bz * L + bm + tid) * NT_STRIDE + blockIdx.x] = tot;
        }
    }
#endif  // !HAS_TCGEN05
}

// ---------------- aux kernels (path-agnostic) ----------------
__global__ void round3_kernel(const float4* __restrict__ q, const float4* __restrict__ k,
                              const float4* __restrict__ w,
                              float4* __restrict__ qr, float4* __restrict__ kr,
                              float4* __restrict__ wr) {
    const size_t nqk = (size_t)BATCH * L * D / 4;
    size_t i = (size_t)blockIdx.x * 256 + threadIdx.x;
    const float4* src;
    float4* dst;
    size_t j;
    if (i < nqk)            { src = q; dst = qr; j = i; }
    else if (i < 2 * nqk)   { src = k; dst = kr; j = i - nqk; }
    else                    { src = w; dst = wr; j = i - 2 * nqk; }
    float4 v = src[j];
    v.x = rna_tf32(v.x); v.y = rna_tf32(v.y); v.z = rna_tf32(v.z); v.w = rna_tf32(v.w);
    dst[j] = v;
}

__global__ void transpose_round_kernel(const float* __restrict__ V, float* __restrict__ VT) {
    __shared__ float t[32][33];
    int b = blockIdx.z;
    int l0 = blockIdx.x * 32, d0 = blockIdx.y * 32;
    int tx = threadIdx.x, ty = threadIdx.y;
    const float* Vb = V + (size_t)b * L * D;
    float* Tb = VT + (size_t)b * D * L;
    #pragma unroll
    for (int i = 0; i < 32; i += 8)
        t[ty + i][tx] = Vb[(size_t)(l0 + ty + i) * D + d0 + tx];
    __syncthreads();
    #pragma unroll
    for (int i = 0; i < 32; i += 8)
        Tb[(size_t)(d0 + ty + i) * L + l0 + tx] = rna_tf32(t[tx][ty + i]);
}

__global__ void reduce_l_kernel(const float* __restrict__ partial, float* __restrict__ linv) {
    int i = blockIdx.x * 256 + threadIdx.x;
    float s = 0.f;
    #pragma unroll
    for (int tIdx = 0; tIdx < NT_STRIDE; tIdx++) s += partial[(size_t)i * NT_STRIDE + tIdx];
    linv[i] = (s > 0.f) ? (1.0f / s) : 0.f;
}

__global__ void scale_att_kernel(float4* __restrict__ att, const float* __restrict__ linv) {
    size_t i = (size_t)blockIdx.x * 256 + threadIdx.x;
    float f = linv[i >> 9];
    float4 v = att[i];
    v.x = rna_tf32(v.x * f); v.y = rna_tf32(v.y * f);
    v.z = rna_tf32(v.z * f); v.w = rna_tf32(v.w * f);
    att[i] = v;
}

extern "C" void kernel_launch(void* const* d_in, const int* in_sizes, int n_in,
                              void* d_out, int out_size)
{
    const float* dq   = (const float*)d_in[0];
    const float* dk   = (const float*)d_in[1];
    const float* dv   = (const float*)d_in[2];
    const int*   dkli = (const int*)d_in[3];
    const float* dW   = (const float*)d_in[4];
    float* d_o   = (float*)d_out;
    float* d_att = d_o + (size_t)BATCH * L * D;

    float *pKT, *pVT, *pQr, *pKr, *pWr, *pPart, *pLinv;
    cudaGetSymbolAddress((void**)&pKT,   g_KT);
    cudaGetSymbolAddress((void**)&pVT,   g_VT);
    cudaGetSymbolAddress((void**)&pQr,   g_Qr);
    cudaGetSymbolAddress((void**)&pKr,   g_Kr);
    cudaGetSymbolAddress((void**)&pWr,   g_Wr);
    cudaGetSymbolAddress((void**)&pPart, g_partial);
    cudaGetSymbolAddress((void**)&pLinv, g_linv);

    cudaFuncSetAttribute(gemm_tc<0>, cudaFuncAttributeMaxDynamicSharedMemorySize, SMEM_TC);
    cudaFuncSetAttribute(gemm_tc<1>, cudaFuncAttributeMaxDynamicSharedMemorySize, SMEM_TC);
    cudaFuncSetAttribute(gemm_tc<2>, cudaFuncAttributeMaxDynamicSharedMemorySize, SMEM_TC);
    cudaFuncSetAttribute(gemm_fb<0>, cudaFuncAttributeMaxDynamicSharedMemorySize, SMEM_FB);
    cudaFuncSetAttribute(gemm_fb<1>, cudaFuncAttributeMaxDynamicSharedMemorySize, SMEM_FB);
    cudaFuncSetAttribute(gemm_fb<2>, cudaFuncAttributeMaxDynamicSharedMemorySize, SMEM_FB);

    const size_t nqk4 = (size_t)BATCH * L * D / 4;
    const size_t nw4  = (size_t)D * D / 4;

    // 0) round Q, K, W to tf32 (one fused pass); VT = round(V^T)
    round3_kernel<<<(int)((2 * nqk4 + nw4) / 256), 256>>>(
        (const float4*)dq, (const float4*)dk, (const float4*)dW,
        (float4*)pQr, (float4*)pKr, (float4*)pWr);                                    // 0
    transpose_round_kernel<<<dim3(L / 32, D / 32, BATCH), dim3(32, 8)>>>(dv, pVT);    // 1

    // 1) KT = round(tanh(K @ W^T))  — one of tc/fb does work per compiled arch
    gemm_fb<0><<<dim3(D / 128, L / 128, BATCH), 256, SMEM_FB>>>(                      // 2
        pKr, pWr, pKT, D, D, D, D, (size_t)L * D, 0, (size_t)L * D, nullptr, 0, nullptr);
    gemm_tc<0><<<dim3(D / 256, L / 256, BATCH), 256, SMEM_TC>>>(                      // 3
        pKr, pWr, pKT, D, D, D, D, (size_t)L * D, 0, (size_t)L * D, nullptr, 0, nullptr);

    // 2) p = exp(Q.KT^T/32 - 26) masked + per-tile row sums -> d_att
    gemm_fb<1><<<dim3(L / 128, L / 128, BATCH), 256, SMEM_FB>>>(                      // 4
        pQr, pKT, d_att, D, D, D, L,
        (size_t)L * D, (size_t)L * D, (size_t)L * L, dkli, L, pPart);
    gemm_tc<1><<<dim3(L / 256, L / 256, BATCH), 256, SMEM_TC>>>(                      // 5 <- profiled
        pQr, pKT, d_att, D, D, D, L,
        (size_t)L * D, (size_t)L * D, (size_t)L * L, dkli, L, pPart);

    // 3) linv = 1 / row sums
    reduce_l_kernel<<<BATCH * L / 256, 256>>>(pPart, pLinv);

    // 4) att = round_tf32(p * linv) in place
    scale_att_kernel<<<(int)((size_t)BATCH * L * L / 4 / 256), 256>>>((float4*)d_att, pLinv);

    // 5) out = att @ V  (B = VT, K-major)
    gemm_fb<2><<<dim3(D / 128, L / 128, BATCH), 256, SMEM_FB>>>(
        d_att, pVT, d_o, L, L, L, D,
        (size_t)L * L, (size_t)L * D, (size_t)L * D, nullptr, 0, nullptr);
    gemm_tc<2><<<dim3(D / 256, L / 256, BATCH), 256, SMEM_TC>>>(
        d_att, pVT, d_o, L, L, L, D,
        (size_t)L * L, (size_t)L * D, (size_t)L * D, nullptr, 0, nullptr);
}

// round 11
// speedup vs baseline: 1.8268x; 1.3592x over previous
#include <cuda_runtime.h>
#include <cstdint>

#define DEV_INLINE __device__ __forceinline__

#if defined(__CUDA_ARCH__) && defined(__CUDA_ARCH_FEAT_SM103_ALL)
#define HAS_TCGEN05 1
#else
#define HAS_TCGEN05 0
#endif

constexpr int BATCH = 16;
constexpr int L = 2048;
constexpr int D = 1024;
constexpr int NT_STRIDE = 16;       // partial-sum slots per row
constexpr int STAGES = 3;
constexpr int STAGE_BYTES = 65536;  // 32KB A + 32KB B
constexpr int SMEM_TC = 1024 + STAGES * STAGE_BYTES;      // 197632
constexpr int SMEM_FB = (4 * 128 * 36) * 4;               // 73728

// ---- scratch (static: no cudaMalloc allowed) ----
__device__ float g_KT[(size_t)BATCH * L * D];
__device__ float g_VT[(size_t)BATCH * D * L];
__device__ float g_Qr[(size_t)BATCH * L * D];
__device__ float g_Kr[(size_t)BATCH * L * D];
__device__ float g_Wr[(size_t)D * D];
__device__ float g_partial[(size_t)BATCH * L * NT_STRIDE];  // zero-init
__device__ float g_linv[(size_t)BATCH * L];

// ---------------- common helpers ----------------
DEV_INLINE uint32_t f2tf(float f) {
    uint32_t u;
    asm("cvt.rna.tf32.f32 %0, %1;" : "=r"(u) : "f"(f));
    return u;
}
DEV_INLINE float rna_tf32(float f) { return __uint_as_float(f2tf(f)); }

DEV_INLINE uint32_t smem_u32(const void* p) {
    uint32_t a;
    asm("{ .reg .u64 t; cvta.to.shared.u64 t, %1; cvt.u32.u64 %0, t; }" : "=r"(a) : "l"(p));
    return a;
}
DEV_INLINE void cp16(uint32_t s, const float* g) {
    asm volatile("cp.async.cg.shared.global [%0], [%1], 16;" :: "r"(s), "l"(g));
}
DEV_INLINE void cp16p(float* s, const float* g) {
    uint32_t sa = (uint32_t)__cvta_generic_to_shared(s);
    asm volatile("cp.async.cg.shared.global [%0], [%1], 16;" :: "r"(sa), "l"(g));
}
DEV_INLINE void cp_commit() { asm volatile("cp.async.commit_group;" ::: "memory"); }
template <int N> DEV_INLINE void cp_wait() {
    asm volatile("cp.async.wait_group %0;" :: "n"(N) : "memory");
}
DEV_INLINE uint32_t swz(uint32_t o) { return o ^ ((o >> 3) & 0x70); }

// =====================================================================
// tcgen05 cg1 path (only materialized for compute_103a)
// =====================================================================
#if HAS_TCGEN05
DEV_INLINE uint32_t elect_one() {
    uint32_t p;
    asm volatile("{ .reg .pred P; elect.sync _|P, 0xFFFFFFFF; selp.b32 %0, 1, 0, P; }" : "=r"(p));
    return p;
}
DEV_INLINE void mbar_init(uint32_t m, uint32_t cnt) {
    asm volatile("mbarrier.init.shared.b64 [%0], %1;" :: "r"(m), "r"(cnt) : "memory");
}
DEV_INLINE void mbar_wait(uint32_t m, uint32_t parity) {
    asm volatile(
        "{\n\t.reg .pred P;\n\t"
        "WL%=:\n\t"
        "mbarrier.try_wait.parity.acquire.cta.shared::cta.b64 P, [%0], %1, 0x989680;\n\t"
        "@P bra.uni WD%=;\n\t"
        "bra.uni WL%=;\n\t"
        "WD%=:\n\t}"
        :: "r"(m), "r"(parity) : "memory");
}
DEV_INLINE void mbar_arrive_rel(uint32_t m) {
    asm volatile("mbarrier.arrive.release.cta.shared::cta.b64 _, [%0];"
                 :: "r"(m) : "memory");
}
DEV_INLINE void tmem_alloc(uint32_t smem_dst, uint32_t ncols) {
    asm volatile("tcgen05.alloc.cta_group::1.sync.aligned.shared::cta.b32 [%0], %1;"
                 :: "r"(smem_dst), "r"(ncols) : "memory");
}
DEV_INLINE void tmem_dealloc(uint32_t tmem, uint32_t ncols) {
    asm volatile("tcgen05.dealloc.cta_group::1.sync.aligned.b32 %0, %1;" :: "r"(tmem), "r"(ncols));
}
DEV_INLINE void tmem_relinquish() {
    asm volatile("tcgen05.relinquish_alloc_permit.cta_group::1.sync.aligned;");
}
DEV_INLINE void mma_tf32_ss(uint32_t d, uint64_t a, uint64_t b, uint32_t idesc, uint32_t en) {
    asm volatile(
        "{\n\t.reg .pred p;\n\t"
        "setp.ne.u32 p, %5, 0;\n\t"
        "tcgen05.mma.cta_group::1.kind::tf32 [%0], %1, %2, %3, {%4,%4,%4,%4}, p;\n\t}"
        :: "r"(d), "l"(a), "l"(b), "r"(idesc), "r"(0u), "r"(en) : "memory");
}
DEV_INLINE void tc_commit(uint32_t mbar) {
    asm volatile("tcgen05.commit.cta_group::1.mbarrier::arrive::one.shared::cluster.b64 [%0];"
                 :: "r"(mbar) : "memory");
}
DEV_INLINE void fence_async() { asm volatile("fence.proxy.async.shared::cta;" ::: "memory"); }
DEV_INLINE void tc_fence_after() { asm volatile("tcgen05.fence::after_thread_sync;" ::: "memory"); }
DEV_INLINE void tc_wait_ld() { asm volatile("tcgen05.wait::ld.sync.aligned;" ::: "memory"); }

#define LDTM32(r, addr)                                                        \
    asm volatile("tcgen05.ld.sync.aligned.32x32b.x32.b32 "                      \
        "{%0,%1,%2,%3,%4,%5,%6,%7,%8,%9,%10,%11,%12,%13,%14,%15,"               \
        "%16,%17,%18,%19,%20,%21,%22,%23,%24,%25,%26,%27,%28,%29,%30,%31}, [%32];" \
        : "=r"((r)[0]), "=r"((r)[1]), "=r"((r)[2]), "=r"((r)[3]),               \
          "=r"((r)[4]), "=r"((r)[5]), "=r"((r)[6]), "=r"((r)[7]),               \
          "=r"((r)[8]), "=r"((r)[9]), "=r"((r)[10]), "=r"((r)[11]),             \
          "=r"((r)[12]), "=r"((r)[13]), "=r"((r)[14]), "=r"((r)[15]),           \
          "=r"((r)[16]), "=r"((r)[17]), "=r"((r)[18]), "=r"((r)[19]),           \
          "=r"((r)[20]), "=r"((r)[21]), "=r"((r)[22]), "=r"((r)[23]),           \
          "=r"((r)[24]), "=r"((r)[25]), "=r"((r)[26]), "=r"((r)[27]),           \
          "=r"((r)[28]), "=r"((r)[29]), "=r"((r)[30]), "=r"((r)[31])            \
        : "r"(addr))

constexpr uint64_t DESC_BASE_SW128 =
    (2ULL << 61) | (1ULL << 46) | (64ULL << 32) | (1ULL << 16);
// idesc kind::tf32: dtype=F32(1)<<4, atype=TF32(2)<<7, btype=TF32(2)<<10,
// N=256: (N>>3)<<17, M=128: (M>>4)<<24
constexpr uint32_t IDESC_TF32 = (1u << 4) | (2u << 7) | (2u << 10) | (32u << 17) | (8u << 24);
#endif  // HAS_TCGEN05

// ---------------------------------------------------------------------------
// tcgen05 cg1 tf32 SS GEMM, 256x256 CTA tile, BK=32, 3-stage ring.
// Warp-specialized mbarrier pipeline (no per-iteration __syncthreads):
//   producers (all 8 warps): cp.async ring, arrive full[s] (count 8),
//   recycle buffers via empty[s] (armed by tcgen05.commit).
//   MMA (elected thread of warp 0): wait full[s] -> 8 dispatches -> commit.
// EPI: 0 = tf32-rounded tanh, 1 = p=exp(s/32-26) masked + row sums, 2 = identity
// ---------------------------------------------------------------------------
template <int EPI>
__global__ void __launch_bounds__(256, 1)
gemm_tc(const float* __restrict__ Ag, const float* __restrict__ Bg,
        float* __restrict__ Cg,
        int Kdim, int lda, int ldb, int ldc,
        size_t strA, size_t strB, size_t strC,
        const int* __restrict__ kli, int kn, float* __restrict__ partial)
{
#if HAS_TCGEN05
    extern __shared__ char smem[];
    const uint32_t su = smem_u32(smem);
    const int tid = threadIdx.x;
    const int wid = tid >> 5;
    const int lane = tid & 31;
    const int bn = blockIdx.x * 256;
    const int bm = blockIdx.y * 256;
    const int bz = blockIdx.z;

    const uint32_t FULL = su + 8;     // full[i] = FULL + 8*i   (count 8)
    const uint32_t EMPT = su + 32;    // empty[i] = EMPT + 8*i  (count 1)
    const uint32_t DONE = su + 56;    // done            (count 1)

    const float* Ab = Ag + (size_t)bz * strA;
    const float* Bb = Bg + (size_t)bz * strB;
    float* Cb = Cg + (size_t)bz * strC;

    if (wid == 0) { tmem_alloc(su, 512); tmem_relinquish(); }
    if (tid == 0) {
        #pragma unroll
        for (int i = 0; i < STAGES; i++) {
            mbar_init(FULL + i * 8, 8);
            mbar_init(EMPT + i * 8, 1);
        }
        mbar_init(DONE, 1);
    }
    __syncthreads();
    uint32_t tb;
    asm volatile("ld.shared.b32 %0, [%1];" : "=r"(tb) : "r"(su));

    const int NKT = Kdim >> 5;

    auto load_stage = [&](int kt, int s) {
        uint32_t abase = su + 1024 + s * STAGE_BYTES;
        uint32_t bbase = abase + 32768;
        const float* As = Ab + (size_t)bm * lda + kt * 32;
        const float* Bs = Bb + (size_t)bn * ldb + kt * 32;
        #pragma unroll
        for (int p = 0; p < 8; p++) {
            int idx = tid + p * 256;
            int row = idx >> 3, c16 = idx & 7;
            cp16(abase + swz(row * 128 + c16 * 16), As + (size_t)row * lda + c16 * 4);
        }
        #pragma unroll
        for (int p = 0; p < 8; p++) {
            int idx = tid + p * 256;
            int row = idx >> 3, c16 = idx & 7;
            cp16(bbase + swz(row * 128 + c16 * 16), Bs + (size_t)row * ldb + c16 * 4);
        }
    };

    uint32_t ecp = 0;             // per-buffer empty parities (bits 0..2)
    uint32_t pf  = 0;             // per-buffer full parities (MMA thread)
    load_stage(0, 0); cp_commit();
    load_stage(1, 1); cp_commit();

    for (int kt = 0; kt < NKT; kt++) {
        const int s = kt % 3;
        // --- stage kt ready: publish to MMA ---
        cp_wait<1>();             // my lanes' stage-kt group retired
        __syncwarp();
        if (lane == 0) mbar_arrive_rel(FULL + s * 8);
        // --- MMA dispatch (elected thread of warp 0) ---
        if (wid == 0) {
            if (elect_one()) {
                mbar_wait(FULL + s * 8, (pf >> s) & 1);
                fence_async();
                uint32_t abase = su + 1024 + s * STAGE_BYTES;
                uint64_t ad = DESC_BASE_SW128 | ((abase >> 4) & 0x3FFF);
                uint64_t bd = DESC_BASE_SW128 | (((abase + 32768) >> 4) & 0x3FFF);
                #pragma unroll
                for (int k8 = 0; k8 < 4; k8++) {
                    uint32_t en = (kt > 0 || k8 > 0) ? 1u : 0u;
                    mma_tf32_ss(tb,       ad + k8 * 2,        bd + k8 * 2, IDESC_TF32, en);
                    mma_tf32_ss(tb + 256, ad + 1024 + k8 * 2, bd + k8 * 2, IDESC_TF32, en);
                }
                tc_commit(EMPT + s * 8);
            }
            pf ^= 1u << s;        // warp-uniform parity update
        }
        // --- prefetch stage kt+2 ---
        if (kt + 2 < NKT) {
            const int nb = (kt + 2) % 3;
            if (kt >= 1) {        // buffer nb consumed by MMA(kt-1)
                mbar_wait(EMPT + nb * 8, (ecp >> nb) & 1);
                ecp ^= 1u << nb;
            }
            load_stage(kt + 2, nb);
        }
        cp_commit();
    }

    // drain: commit with no new MMAs waits for ALL prior MMAs
    if (wid == 0 && elect_one()) tc_commit(DONE);
    mbar_wait(DONE, 0);
    tc_fence_after();
    __syncthreads();

    // ---------------- epilogue: TMEM -> smem -> coalesced gmem ----------------
    float* stg = (float*)(smem + 1024);                 // 128 x 36 floats
    int* mk = (int*)(smem + 1024 + 128 * 36 * 4);       // 256 mask ints
    if (EPI == 1) mk[tid] = kli[(size_t)bz * kn + bn + tid];
    __syncthreads();

    float rs[2] = {0.f, 0.f};
    #pragma unroll 1
    for (int h = 0; h < 2; h++) {
        #pragma unroll 1
        for (int cb = 0; cb < 256; cb += 32) {
            if (wid < 4) {
                uint32_t r[32];
                LDTM32(r, tb + h * 256 + cb);
                tc_wait_ld();
                float v[32];
                #pragma unroll
                for (int j = 0; j < 32; j++) {
                    float x = __uint_as_float(r[j]);
                    if (EPI == 0) {
                        v[j] = rna_tf32(tanhf(x));
                    } else if (EPI == 1) {
                        float m = (mk[cb + j] == 0) ? 0.f : 1.f;
                        v[j] = m * __expf(x * 0.03125f - 26.f);
                        rs[h] += v[j];
                    } else {
                        v[j] = x;
                    }
                }
                int row = wid * 32 + lane;
                #pragma unroll
                for (int j4 = 0; j4 < 8; j4++) {
                    *(float4*)&stg[row * 36 + j4 * 4] =
                        make_float4(v[j4 * 4], v[j4 * 4 + 1], v[j4 * 4 + 2], v[j4 * 4 + 3]);
                }
            }
            __syncthreads();
            #pragma unroll
            for (int p = 0; p < 4; p++) {
                int idx = tid + p * 256;
                int r2 = idx >> 3, c4 = idx & 7;
                float4 val = *(float4*)&stg[r2 * 36 + c4 * 4];
                *(float4*)&Cb[(size_t)(bm + h * 128 + r2) * ldc + bn + cb + c4 * 4] = val;
            }
            __syncthreads();
        }
    }

    if (EPI == 1 && wid < 4) {
        #pragma unroll
        for (int h = 0; h < 2; h++) {
            size_t row = (size_t)bz * L + bm + h * 128 + wid * 32 + lane;
            partial[row * NT_STRIDE + blockIdx.x] = rs[h];
        }
    }

    __syncthreads();
    if (wid == 0) tmem_dealloc(tb, 512);
#endif  // HAS_TCGEN05
}

// ---------------------------------------------------------------------------
// Fallback: mma.sync tf32, 128x128 tile (compute_103 builds only).
// ---------------------------------------------------------------------------
DEV_INLINE void mma_tf32_sync(float c[4], const uint32_t a[4], const uint32_t b[2]) {
    asm volatile(
        "mma.sync.aligned.m16n8k8.row.col.f32.tf32.tf32.f32 "
        "{%0,%1,%2,%3},{%4,%5,%6,%7},{%8,%9},{%0,%1,%2,%3};"
        : "+f"(c[0]), "+f"(c[1]), "+f"(c[2]), "+f"(c[3])
        : "r"(a[0]), "r"(a[1]), "r"(a[2]), "r"(a[3]), "r"(b[0]), "r"(b[1]));
}

template <int EPI>
__global__ void __launch_bounds__(256, 2)
gemm_fb(const float* __restrict__ Ag, const float* __restrict__ Bg,
        float* __restrict__ Cg,
        int Kdim, int lda, int ldb, int ldc,
        size_t strA, size_t strB, size_t strC,
        const int* __restrict__ kli, int kn, float* __restrict__ partial)
{
#if !HAS_TCGEN05
    extern __shared__ float sm[];
    constexpr int ASZ = 128 * 36;
    float* shA = sm;
    float* shB = sm + 2 * ASZ;

    const int tid  = threadIdx.x;
    const int lane = tid & 31;
    const int warp = tid >> 5;
    const int g = lane >> 2;
    const int t = lane & 3;
    const int wm = (warp >> 2) * 64;
    const int wn = (warp & 3) * 32;
    const int bm = blockIdx.y * 128;
    const int bn = blockIdx.x * 128;
    const int bz = blockIdx.z;

    const float* Ab = Ag + (size_t)bz * strA;
    const float* Bb = Bg + (size_t)bz * strB;
    float* Cb = Cg + (size_t)bz * strC;

    float acc[4][4][4];
    #pragma unroll
    for (int mi = 0; mi < 4; mi++)
        #pragma unroll
        for (int ni = 0; ni < 4; ni++)
            #pragma unroll
            for (int e = 0; e < 4; e++) acc[mi][ni][e] = 0.f;

    const int nkt = Kdim >> 5;

    auto load_stage = [&](int kt, int buf) {
        float* dA = shA + buf * ASZ;
        float* dB = shB + buf * ASZ;
        const float* sA = Ab + (size_t)bm * lda + kt * 32;
        const float* sB = Bb + (size_t)bn * ldb + kt * 32;
        #pragma unroll
        for (int p = 0; p < 4; p++) {
            int e = tid + p * 256;
            int r = e >> 3, q4 = (e & 7) << 2;
            cp16p(dA + r * 36 + q4, sA + (size_t)r * lda + q4);
        }
        #pragma unroll
        for (int p = 0; p < 4; p++) {
            int e = tid + p * 256;
            int r = e >> 3, q4 = (e & 7) << 2;
            cp16p(dB + r * 36 + q4, sB + (size_t)r * ldb + q4);
        }
    };

    auto compute = [&](int buf) {
        const uint32_t* a0 = (const uint32_t*)(shA + buf * ASZ);
        const uint32_t* b0 = (const uint32_t*)(shB + buf * ASZ);
        #pragma unroll
        for (int kk = 0; kk < 4; ++kk) {
            const int c = kk * 8 + t;
            uint32_t af[4][4];
            #pragma unroll
            for (int mi = 0; mi < 4; mi++) {
                const int r = wm + mi * 16 + g;
                af[mi][0] = a0[r * 36 + c];
                af[mi][1] = a0[(r + 8) * 36 + c];
                af[mi][2] = a0[r * 36 + c + 4];
                af[mi][3] = a0[(r + 8) * 36 + c + 4];
            }
            uint32_t bf[4][2];
            #pragma unroll
            for (int ni = 0; ni < 4; ni++) {
                const int n = wn + ni * 8 + g;
                bf[ni][0] = b0[n * 36 + c];
                bf[ni][1] = b0[n * 36 + c + 4];
            }
            #pragma unroll
            for (int mi = 0; mi < 4; mi++)
                #pragma unroll
                for (int ni = 0; ni < 4; ni++)
                    mma_tf32_sync(acc[mi][ni], af[mi], bf[ni]);
        }
    };

    load_stage(0, 0);
    cp_commit();
    for (int kt = 0; kt < nkt; ++kt) {
        int buf = kt & 1;
        if (kt + 1 < nkt) {
            load_stage(kt + 1, buf ^ 1);
            cp_commit();
            cp_wait<1>();
        } else {
            cp_wait<0>();
        }
        __syncthreads();
        compute(buf);
        __syncthreads();
    }

    if (EPI == 0 || EPI == 2) {
        #pragma unroll
        for (int mi = 0; mi < 4; mi++) {
            const int r0 = bm + wm + mi * 16 + g;
            #pragma unroll
            for (int ni = 0; ni < 4; ni++) {
                const int cl = bn + wn + ni * 8 + 2 * t;
                float2 v0, v1;
                if (EPI == 0) {
                    v0.x = rna_tf32(tanhf(acc[mi][ni][0]));
                    v0.y = rna_tf32(tanhf(acc[mi][ni][1]));
                    v1.x = rna_tf32(tanhf(acc[mi][ni][2]));
                    v1.y = rna_tf32(tanhf(acc[mi][ni][3]));
                } else {
                    v0.x = acc[mi][ni][0]; v0.y = acc[mi][ni][1];
                    v1.x = acc[mi][ni][2]; v1.y = acc[mi][ni][3];
                }
                *(float2*)(Cb + (size_t)r0 * ldc + cl) = v0;
                *(float2*)(Cb + (size_t)(r0 + 8) * ldc + cl) = v1;
            }
        }
    } else {
        int* mk = (int*)sm;
        float* red = sm + 128;
        if (tid < 128) mk[tid] = kli[(size_t)bz * kn + bn + tid];
        __syncthreads();

        float rsv[4][2];
        #pragma unroll
        for (int mi = 0; mi < 4; mi++) { rsv[mi][0] = 0.f; rsv[mi][1] = 0.f; }

        #pragma unroll
        for (int mi = 0; mi < 4; mi++) {
            const int r0 = bm + wm + mi * 16 + g;
            #pragma unroll
            for (int ni = 0; ni < 4; ni++) {
                const int cl = wn + ni * 8 + 2 * t;
                const float m0 = (mk[cl] == 0) ? 0.f : 1.f;
                const float m1 = (mk[cl + 1] == 0) ? 0.f : 1.f;
                float p00 = m0 * __expf(acc[mi][ni][0] * 0.03125f - 26.f);
                float p01 = m1 * __expf(acc[mi][ni][1] * 0.03125f - 26.f);
                float p10 = m0 * __expf(acc[mi][ni][2] * 0.03125f - 26.f);
                float p11 = m1 * __expf(acc[mi][ni][3] * 0.03125f - 26.f);
                float2 v0 = {p00, p01}, v1 = {p10, p11};
                *(float2*)(Cb + (size_t)r0 * ldc + bn + cl) = v0;
                *(float2*)(Cb + (size_t)(r0 + 8) * ldc + bn + cl) = v1;
                rsv[mi][0] += p00 + p01;
                rsv[mi][1] += p10 + p11;
            }
        }
        #pragma unroll
        for (int mi = 0; mi < 4; mi++) {
            #pragma unroll
            for (int h = 0; h < 2; h++) {
                float vsum = rsv[mi][h];
                vsum += __shfl_xor_sync(0xffffffffu, vsum, 1);
                vsum += __shfl_xor_sync(0xffffffffu, vsum, 2);
                if (t == 0)
                    red[(warp & 3) * 128 + wm + mi * 16 + g + h * 8] = vsum;
            }
        }
        __syncthreads();
        if (tid < 128) {
            float tot = red[tid] + red[128 + tid] + red[256 + tid] + red[384 + tid];
            partial[(size_t)(bz * L + bm + tid) * NT_STRIDE + blockIdx.x] = tot;
        }
    }
#endif  // !HAS_TCGEN05
}

// ---------------- aux kernels (path-agnostic, R7-exact) ----------------
__global__ void round_tf32_kernel(const float4* __restrict__ src, float4* __restrict__ dst) {
    size_t i = (size_t)blockIdx.x * 256 + threadIdx.x;
    float4 v = src[i];
    v.x = rna_tf32(v.x); v.y = rna_tf32(v.y); v.z = rna_tf32(v.z); v.w = rna_tf32(v.w);
    dst[i] = v;
}

__global__ void transpose_round_kernel(const float* __restrict__ V, float* __restrict__ VT) {
    __shared__ float t[32][33];
    int b = blockIdx.z;
    int l0 = blockIdx.x * 32, d0 = blockIdx.y * 32;
    int tx = threadIdx.x, ty = threadIdx.y;
    const float* Vb = V + (size_t)b * L * D;
    float* Tb = VT + (size_t)b * D * L;
    #pragma unroll
    for (int i = 0; i < 32; i += 8)
        t[ty + i][tx] = Vb[(size_t)(l0 + ty + i) * D + d0 + tx];
    __syncthreads();
    #pragma unroll
    for (int i = 0; i < 32; i += 8)
        Tb[(size_t)(d0 + ty + i) * L + l0 + tx] = rna_tf32(t[tx][ty + i]);
}

__global__ void reduce_l_kernel(const float* __restrict__ partial, float* __restrict__ linv) {
    int i = blockIdx.x * 256 + threadIdx.x;
    float s = 0.f;
    #pragma unroll
    for (int tIdx = 0; tIdx < NT_STRIDE; tIdx++) s += partial[(size_t)i * NT_STRIDE + tIdx];
    linv[i] = (s > 0.f) ? (1.0f / s) : 0.f;
}

__global__ void scale_att_kernel(float4* __restrict__ att, const float* __restrict__ linv) {
    size_t i = (size_t)blockIdx.x * 256 + threadIdx.x;
    float f = linv[i >> 9];
    float4 v = att[i];
    v.x = rna_tf32(v.x * f); v.y = rna_tf32(v.y * f);
    v.z = rna_tf32(v.z * f); v.w = rna_tf32(v.w * f);
    att[i] = v;
}

extern "C" void kernel_launch(void* const* d_in, const int* in_sizes, int n_in,
                              void* d_out, int out_size)
{
    const float* dq   = (const float*)d_in[0];
    const float* dk   = (const float*)d_in[1];
    const float* dv   = (const float*)d_in[2];
    const int*   dkli = (const int*)d_in[3];
    const float* dW   = (const float*)d_in[4];
    float* d_o   = (float*)d_out;
    float* d_att = d_o + (size_t)BATCH * L * D;

    float *pKT, *pVT, *pQr, *pKr, *pWr, *pPart, *pLinv;
    cudaGetSymbolAddress((void**)&pKT,   g_KT);
    cudaGetSymbolAddress((void**)&pVT,   g_VT);
    cudaGetSymbolAddress((void**)&pQr,   g_Qr);
    cudaGetSymbolAddress((void**)&pKr,   g_Kr);
    cudaGetSymbolAddress((void**)&pWr,   g_Wr);
    cudaGetSymbolAddress((void**)&pPart, g_partial);
    cudaGetSymbolAddress((void**)&pLinv, g_linv);

    cudaFuncSetAttribute(gemm_tc<0>, cudaFuncAttributeMaxDynamicSharedMemorySize, SMEM_TC);
    cudaFuncSetAttribute(gemm_tc<1>, cudaFuncAttributeMaxDynamicSharedMemorySize, SMEM_TC);
    cudaFuncSetAttribute(gemm_tc<2>, cudaFuncAttributeMaxDynamicSharedMemorySize, SMEM_TC);
    cudaFuncSetAttribute(gemm_fb<0>, cudaFuncAttributeMaxDynamicSharedMemorySize, SMEM_FB);
    cudaFuncSetAttribute(gemm_fb<1>, cudaFuncAttributeMaxDynamicSharedMemorySize, SMEM_FB);
    cudaFuncSetAttribute(gemm_fb<2>, cudaFuncAttributeMaxDynamicSharedMemorySize, SMEM_FB);

    // 0) round Q, K, W to tf32 (RNA); VT = round(V^T)  — R7-exact aux
    round_tf32_kernel<<<(int)((size_t)BATCH * L * D / 4 / 256), 256>>>((const float4*)dq, (float4*)pQr);   // 0
    round_tf32_kernel<<<(int)((size_t)BATCH * L * D / 4 / 256), 256>>>((const float4*)dk, (float4*)pKr);   // 1
    round_tf32_kernel<<<D * D / 4 / 256, 256>>>((const float4*)dW, (float4*)pWr);                          // 2
    transpose_round_kernel<<<dim3(L / 32, D / 32, BATCH), dim3(32, 8)>>>(dv, pVT);                         // 3

    // 1) KT = round(tanh(K @ W^T))  — one of tc/fb does work per compiled arch
    gemm_fb<0><<<dim3(D / 128, L / 128, BATCH), 256, SMEM_FB>>>(                                            // 4
        pKr, pWr, pKT, D, D, D, D, (size_t)L * D, 0, (size_t)L * D, nullptr, 0, nullptr);
    gemm_tc<0><<<dim3(D / 256, L / 256, BATCH), 256, SMEM_TC>>>(                                            // 5 <- profiled
        pKr, pWr, pKT, D, D, D, D, (size_t)L * D, 0, (size_t)L * D, nullptr, 0, nullptr);

    // 2) p = exp(Q.KT^T/32 - 26) masked + per-tile row sums -> d_att
    gemm_fb<1><<<dim3(L / 128, L / 128, BATCH), 256, SMEM_FB>>>(
        pQr, pKT, d_att, D, D, D, L,
        (size_t)L * D, (size_t)L * D, (size_t)L * L, dkli, L, pPart);
    gemm_tc<1><<<dim3(L / 256, L / 256, BATCH), 256, SMEM_TC>>>(
        pQr, pKT, d_att, D, D, D, L,
        (size_t)L * D, (size_t)L * D, (size_t)L * L, dkli, L, pPart);

    // 3) linv = 1 / row sums
    reduce_l_kernel<<<BATCH * L / 256, 256>>>(pPart, pLinv);

    // 4) att = round_tf32(p * linv) in place
    scale_att_kernel<<<(int)((size_t)BATCH * L * L / 4 / 256), 256>>>((float4*)d_att, pLinv);

    // 5) out = att @ V  (B = VT, K-major)
    gemm_fb<2><<<dim3(D / 128, L / 128, BATCH), 256, SMEM_FB>>>(
        d_att, pVT, d_o, L, L, L, D,
        (size_t)L * L, (size_t)L * D, (size_t)L * D, nullptr, 0, nullptr);
    gemm_tc<2><<<dim3(D / 256, L / 256, BATCH), 256, SMEM_TC>>>(
        d_att, pVT, d_o, L, L, L, D,
        (size_t)L * L, (size_t)L * D, (size_t)L * D, nullptr, 0, nullptr);
}